// round 12
// baseline (speedup 1.0000x reference)
#include <cuda_runtime.h>
#include <cstdint>

// Problem constants (fixed by reference)
#define RDIM 4096
#define TLEN 2048
#define IDIM 8
#define ODIM 8
#define NBLK 128                 // persistent CTAs, co-resident on 148 SMs
#define NTHR 512                 // 16 warps
#define NSLOT (RDIM / 2)         // 2048 warp-slots (2 rows each, 16 lanes/row)
#define SLOTS_PER_CTA 16
#define MAXC 768                 // stage-1 compaction capacity (nnz ~410 +-20)
#define NSUB_MAX 36              // entries per lane: 16*36=576 nnz/row cap (+8.7 sd)
#define NE NSUB_MAX              // register-resident entries per lane
#define H_BYTES (RDIM * 4)       // 16 KB
#define NGRP 4                   // CTA groups / h chunks / mbar arrive count
#define GRP_CTAS (NBLK / NGRP)   // 32 CTAs per group
#define CHUNK_BYTES (H_BYTES / NGRP)   // 4 KB
#define CHUNK_FLOATS (RDIM / NGRP)     // 1024

struct __align__(8) Ent { float v; int c; };

// Scratch (device globals: no allocation allowed)
__device__ __align__(16) Ent g_ellp[NSLOT * NSUB_MAX * 32];  // ~19 MB packed ELL
__device__ Ent      g_rcomp[RDIM * MAXC];                    // stage-1 compaction
__device__ int      g_np[NSLOT];                             // sub-iters per slot
__device__ float    g_u[TLEN * RDIM];                        // Win @ x_t (32 MB)
__device__ __align__(16) float g_hall[(TLEN + 1) * RDIM];    // all hidden states
__device__ unsigned g_arr[NBLK];                             // barrier cells

// STRONG scoped sync (guaranteed visibility; relaxed = no fence)
__device__ __forceinline__ unsigned ld_rlx(const unsigned* p) {
    unsigned v;
    asm volatile("ld.relaxed.gpu.global.u32 %0, [%1];" : "=r"(v) : "l"(p) : "memory");
    return v;
}
__device__ __forceinline__ void red_rel_add(unsigned* p) {
    asm volatile("red.release.gpu.global.add.u32 [%0], 1;" :: "l"(p) : "memory");
}
__device__ __forceinline__ uint32_t smem_u32(const void* p) {
    uint32_t a;
    asm("{ .reg .u64 t; cvta.to.shared.u64 t, %1; cvt.u32.u64 %0, t; }"
        : "=r"(a) : "l"(p));
    return a;
}
__device__ __forceinline__ float tanh_hw(float x) {
    float r;
    asm("tanh.approx.f32 %0, %1;" : "=f"(r) : "f"(x));
    return r;
}

// ---------------------------------------------------------------------------
// K1: u[t][r] = sum_i Win[r,i] * x[t,i]
// ---------------------------------------------------------------------------
__global__ void k_u(const float* __restrict__ x, const float* __restrict__ Win) {
    int t = blockIdx.x;
    __shared__ float xs[IDIM];
    if (threadIdx.x < IDIM) xs[threadIdx.x] = x[t * IDIM + threadIdx.x];
    __syncthreads();
    for (int r = threadIdx.x; r < RDIM; r += blockDim.x) {
        const float4* w = (const float4*)(Win + r * IDIM);
        float4 a = __ldg(&w[0]), b = __ldg(&w[1]);
        g_u[t * RDIM + r] = a.x * xs[0] + a.y * xs[1] + a.z * xs[2] + a.w * xs[3]
                          + b.x * xs[4] + b.y * xs[5] + b.z * xs[6] + b.w * xs[7];
    }
}

// ---------------------------------------------------------------------------
// K2: per slot (one warp): compact 2 rows of W (zeros exact), then lane 0
// greedily assigns each entry a (sub-iter, lane) such that all 32 lanes of a
// sub-iter hit distinct smem banks. Lanes 0-15: row 2s; lanes 16-31: row 2s+1.
// ---------------------------------------------------------------------------
__global__ void k_prep(const float* __restrict__ W) {
    int wid  = threadIdx.x >> 5;
    int lane = threadIdx.x & 31;
    int slot = blockIdx.x * (blockDim.x / 32) + wid;
    if (slot >= NSLOT) return;

    Ent* ell = g_ellp + (size_t)slot * (NSUB_MAX * 32);

    // prefill padding: v=0, col=lane (conflict-free dummies)
    for (int idx = lane; idx < NSUB_MAX * 32; idx += 32)
        ell[idx] = Ent{0.0f, idx & 31};

    int cnts[2];
    for (int half = 0; half < 2; half++) {
        int row = 2 * slot + half;
        const float* wr = W + (size_t)row * RDIM;
        Ent* dst = g_rcomp + (size_t)row * MAXC;
        int cnt = 0;
        for (int c0 = 0; c0 < RDIM; c0 += 32) {
            float v = wr[c0 + lane];
            unsigned bal = __ballot_sync(0xffffffffu, v != 0.0f);
            if (v != 0.0f) {
                int pos = cnt + __popc(bal & ((1u << lane) - 1u));
                if (pos < MAXC) dst[pos] = Ent{v, c0 + lane};
            }
            cnt += __popc(bal);
        }
        cnts[half] = cnt < MAXC ? cnt : MAXC;
    }
    __syncwarp();

    __shared__ int s_mask[8][NSUB_MAX];
    __shared__ int s_cnt[8][2][NSUB_MAX];
    if (lane == 0) {
        int kmax = 0;
        for (int k = 0; k < NSUB_MAX; k++) {
            s_mask[wid][k] = 0;
            s_cnt[wid][0][k] = 0;
            s_cnt[wid][1][k] = 0;
        }
        for (int half = 0; half < 2; half++) {
            int row = 2 * slot + half;
            const Ent* src = g_rcomp + (size_t)row * MAXC;
            int base = 0;
            for (int i = 0; i < cnts[half]; i++) {
                Ent e = src[i];
                int b = e.c & 31;
                while (base < NSUB_MAX && s_cnt[wid][half][base] >= 16) base++;
                if (base >= NSUB_MAX) break;          // statistically never
                int k = -1;
                for (int kk = base; kk < NSUB_MAX; kk++) {
                    if (s_cnt[wid][half][kk] < 16 && !((s_mask[wid][kk] >> b) & 1)) {
                        k = kk; break;
                    }
                }
                if (k < 0) k = base;                   // accept rare conflict
                int j = s_cnt[wid][half][k];
                s_cnt[wid][half][k] = j + 1;
                s_mask[wid][k] |= 1 << b;
                if (k > kmax) kmax = k;
                ell[k * 32 + half * 16 + j] = e;
            }
        }
        g_np[slot] = kmax + 1;
    }
}

// ---------------------------------------------------------------------------
// K3: per-replay init
// ---------------------------------------------------------------------------
__global__ void k_init() {
    int i = blockIdx.x * blockDim.x + threadIdx.x;
    if (i < RDIM) g_hall[i] = 0.0f;   // h_0 = 0
    if (i < NBLK) g_arr[i] = 0u;
}

// ---------------------------------------------------------------------------
// K4 (launch #4 -> ncu target): persistent recurrence, fully de-synchronized
// inner loop: NO __syncthreads, NO fences, only mbar waits.
//   - W entries REGISTER-resident (36 vals + 18 packed byte-offset regs/lane).
//   - h double-buffered in smem (2 x 16 KB): TMA for t+1 writes the buffer
//     the slowest warp is NOT reading (2-step reuse distance is enforced by
//     the release/poll chain; see round-12 analysis).
//   - Per-warp arrive.expect_tx (mbar count = NGRP): no central re-arm.
//   - Two ping-pong mbars: step t uses mbar[t&1], parity (t>>1)&1; an arrive
//     for step t+1 is provably ordered after mbar[(t+1)&1]'s previous phase
//     (step t-1) fully completed.
// ---------------------------------------------------------------------------
__global__ void __launch_bounds__(NTHR, 1)
k_main() {
    __shared__ __align__(16) float sh[2][RDIM];       // 2 x 16 KB h
    __shared__ __align__(8) unsigned long long mbar[2];

    const int tid  = threadIdx.x;
    const int wid  = tid >> 5;
    const int lane = tid & 31;
    const int slot = blockIdx.x * SLOTS_PER_CTA + wid;
    const int half = lane >> 4;
    const int row  = 2 * slot + half;
    const bool head = (lane == 0) | (lane == 16);

    const uint32_t mbar0_a = smem_u32(&mbar[0]);
    const uint32_t mbar1_a = smem_u32(&mbar[1]);
    const uint32_t sh_a    = smem_u32(sh);

    if (tid == 0) {
        asm volatile("mbarrier.init.shared.b64 [%0], %1;"
                     :: "r"(mbar0_a), "r"((unsigned)NGRP) : "memory");
        asm volatile("mbarrier.init.shared.b64 [%0], %1;"
                     :: "r"(mbar1_a), "r"((unsigned)NGRP) : "memory");
        asm volatile("fence.proxy.async;" ::: "memory");
    }

    // one-time: load this lane's 36 entries into registers
    float    vv[NE];
    unsigned cp[NE / 2];   // two pre-scaled byte offsets per reg
    {
        const Ent* src = g_ellp + (size_t)slot * (NSUB_MAX * 32) + lane;
#pragma unroll
        for (int i = 0; i < NE; i += 2) {
            Ent e0 = src[i * 32];
            Ent e1 = src[(i + 1) * 32];
            vv[i]     = e0.v;
            vv[i + 1] = e1.v;
            cp[i >> 1] = ((unsigned)e0.c << 2) | ((unsigned)e1.c << 18);
        }
    }

    float u_next = head ? __ldg(&g_u[row]) : 0.0f;     // u for t=0
    __syncthreads();                                   // mbar init visible

    for (int t = 0; t < TLEN; ++t) {
        const uint32_t mb   = (t & 1) ? mbar1_a : mbar0_a;
        const uint32_t bufo = (unsigned)(t & 1) * (unsigned)H_BYTES;

        // ---- warps 0-3: poll own CTA-group, arm mbar, fetch 4 KB chunk ----
        if (wid < NGRP) {
            if (t) {
                const unsigned tgt = 32u * (unsigned)t;
                const unsigned* cell = &g_arr[GRP_CTAS * wid + lane];
                for (;;) {
                    unsigned v = ld_rlx(cell);
                    if (!__any_sync(0xffffffffu, v < tgt)) break;
                }
            }
            if (lane == 0) {
                asm volatile("mbarrier.arrive.expect_tx.shared.b64 _, [%0], %1;"
                             :: "r"(mb), "r"((unsigned)CHUNK_BYTES) : "memory");
                const float* src = g_hall + (size_t)t * RDIM + wid * CHUNK_FLOATS;
                asm volatile(
                    "cp.async.bulk.shared::cluster.global.mbarrier::complete_tx::bytes "
                    "[%0], [%1], %2, [%3];"
                    :: "r"(sh_a + bufo + wid * CHUNK_BYTES), "l"(src),
                       "r"((unsigned)CHUNK_BYTES), "r"(mb)
                    : "memory");
            }
        }
        // all threads wait for this step's 4 chunks; parity = (t>>1)&1
        {
            const unsigned par = (unsigned)((t >> 1) & 1);
            unsigned done;
            asm volatile(
                "{\n\t.reg .pred p;\n\t"
                "mbarrier.try_wait.parity.acquire.cta.shared::cta.b64 p, [%1], %2;\n\t"
                "selp.b32 %0, 1, 0, p;\n\t}"
                : "=r"(done) : "r"(mb), "r"(par) : "memory");
            if (!done) {
                asm volatile(
                    "{\n\t.reg .pred P1;\n\t"
                    "W%=:\n\t"
                    "mbarrier.try_wait.parity.acquire.cta.shared::cta.b64 P1, [%0], %1, 0x989680;\n\t"
                    "@P1 bra.uni D%=;\n\t"
                    "bra.uni W%=;\n\t"
                    "D%=:\n\t}"
                    :: "r"(mb), "r"(par) : "memory");
            }
        }

        // ---- sparse dot: values/offsets from registers, gathers from smem ----
        const char* hb = (const char*)sh + bufo;
        float a0 = 0.0f, a1 = 0.0f;
#pragma unroll
        for (int i = 0; i < NE; i += 2) {
            unsigned p = cp[i >> 1];
            a0 += vv[i]     * *(const float*)(hb + (p & 0xFFFFu));
            a1 += vv[i + 1] * *(const float*)(hb + (p >> 16));
        }
        float acc = a0 + a1;
#pragma unroll
        for (int off = 8; off; off >>= 1)
            acc += __shfl_xor_sync(0xffffffffu, acc, off);

        if (head) {
            float hv = tanh_hw(acc + u_next);          // HW MUFU.TANH
            __stcg(g_hall + (size_t)(t + 1) * RDIM + row, hv);
            // arrive: release covers own h store; strong -> guaranteed visible
            red_rel_add(&g_arr[blockIdx.x]);
            if (t + 1 < TLEN) u_next = __ldcg(&g_u[(size_t)(t + 1) * RDIM + row]);
        }
        // NO tail sync: double buffering + the 2-step release/poll chain
        // guarantees no warp still reads buf[(t+2)&1 == t&1] when its TMA fires.
    }
}

// ---------------------------------------------------------------------------
// K5: out[t][o] = bias[o] + sum_r h_{t+1}[r] * Wout[o][r]
// ---------------------------------------------------------------------------
__global__ void k_out(const float* __restrict__ Wout, const float* __restrict__ bias,
                      float* __restrict__ out) {
    int t = blockIdx.x;
    const float4* h4 = (const float4*)(g_hall + (size_t)(t + 1) * RDIM);
    float acc[ODIM];
#pragma unroll
    for (int o = 0; o < ODIM; o++) acc[o] = 0.0f;

    for (int r4 = threadIdx.x; r4 < RDIM / 4; r4 += blockDim.x) {
        float4 h = h4[r4];
#pragma unroll
        for (int o = 0; o < ODIM; o++) {
            float4 w = __ldg((const float4*)(Wout + o * RDIM) + r4);
            acc[o] += h.x * w.x + h.y * w.y + h.z * w.z + h.w * w.w;
        }
    }
    __shared__ float red[8][ODIM];
    int wid = threadIdx.x >> 5, lane = threadIdx.x & 31;
#pragma unroll
    for (int o = 0; o < ODIM; o++) {
        float v = acc[o];
#pragma unroll
        for (int off = 16; off; off >>= 1)
            v += __shfl_xor_sync(0xffffffffu, v, off);
        if (lane == 0) red[wid][o] = v;
    }
    __syncthreads();
    if (threadIdx.x < ODIM) {
        float s = bias[threadIdx.x];
#pragma unroll
        for (int w = 0; w < 8; w++) s += red[w][threadIdx.x];
        out[t * ODIM + threadIdx.x] = s;
    }
}

// ---------------------------------------------------------------------------
extern "C" void kernel_launch(void* const* d_in, const int* in_sizes, int n_in,
                              void* d_out, int out_size) {
    (void)in_sizes; (void)n_in; (void)out_size;
    const float* x      = (const float*)d_in[0];  // [1, 2048, 8]
    const float* Win    = (const float*)d_in[1];  // [4096, 8]
    const float* W      = (const float*)d_in[2];  // [4096, 4096]
    const float* Wout_w = (const float*)d_in[3];  // [8, 4096]
    const float* Wout_b = (const float*)d_in[4];  // [8]
    float* out = (float*)d_out;                   // [1, 2048, 8]

    k_u<<<TLEN, 256>>>(x, Win);                   // launch 1
    k_prep<<<NSLOT / 8, 256>>>(W);                // launch 2
    k_init<<<(RDIM + 255) / 256, 256>>>();        // launch 3
    k_main<<<NBLK, NTHR>>>();                     // launch 4 <- ncu target
    k_out<<<TLEN, 256>>>(Wout_w, Wout_b, out);    // launch 5
}

// round 13
// speedup vs baseline: 1.1594x; 1.1594x over previous
#include <cuda_runtime.h>
#include <cstdint>

// Problem constants (fixed by reference)
#define RDIM 4096
#define TLEN 2048
#define IDIM 8
#define ODIM 8
#define NBLK 128                 // persistent CTAs, co-resident on 148 SMs
#define NTHR 512                 // 16 warps
#define NSLOT (RDIM / 2)         // 2048 warp-slots (2 rows each, 16 lanes/row)
#define SLOTS_PER_CTA 16
#define MAXC 768                 // stage-1 compaction capacity (nnz ~410 +-20)
#define NSUB_MAX 36              // entries per lane: 16*36=576 nnz/row cap (+8.7 sd)
#define NE NSUB_MAX              // register-resident entries per lane
#define H_BYTES (RDIM * 4)       // 16 KB
#define NGRP 4                   // CTA groups / h chunks
#define GRP_CTAS (NBLK / NGRP)   // 32 CTAs per group
#define CHUNK_BYTES (H_BYTES / NGRP)   // 4 KB
#define CHUNK_FLOATS (RDIM / NGRP)     // 1024
#define CELL_STRIDE 32           // one 128B line per barrier cell (L2-slice spread)

struct __align__(8) Ent { float v; int c; };

// Scratch (device globals: no allocation allowed)
__device__ __align__(16) Ent g_ellp[NSLOT * NSUB_MAX * 32];  // ~19 MB packed ELL
__device__ Ent      g_rcomp[RDIM * MAXC];                    // stage-1 compaction
__device__ int      g_np[NSLOT];                             // sub-iters per slot
__device__ float    g_u[TLEN * RDIM];                        // Win @ x_t (32 MB)
__device__ __align__(16) float g_hall[(TLEN + 1) * RDIM];    // all hidden states
__device__ __align__(128) unsigned g_arr[NBLK * CELL_STRIDE]; // padded barrier cells

// STRONG scoped sync (guaranteed visibility; relaxed = no fence)
__device__ __forceinline__ unsigned ld_rlx(const unsigned* p) {
    unsigned v;
    asm volatile("ld.relaxed.gpu.global.u32 %0, [%1];" : "=r"(v) : "l"(p) : "memory");
    return v;
}
__device__ __forceinline__ void red_rel_add(unsigned* p) {
    asm volatile("red.release.gpu.global.add.u32 [%0], 1;" :: "l"(p) : "memory");
}
__device__ __forceinline__ uint32_t smem_u32(const void* p) {
    uint32_t a;
    asm("{ .reg .u64 t; cvta.to.shared.u64 t, %1; cvt.u32.u64 %0, t; }"
        : "=r"(a) : "l"(p));
    return a;
}
__device__ __forceinline__ float tanh_hw(float x) {
    float r;
    asm("tanh.approx.f32 %0, %1;" : "=f"(r) : "f"(x));
    return r;
}

// ---------------------------------------------------------------------------
// K1: u[t][r] = sum_i Win[r,i] * x[t,i]
// ---------------------------------------------------------------------------
__global__ void k_u(const float* __restrict__ x, const float* __restrict__ Win) {
    int t = blockIdx.x;
    __shared__ float xs[IDIM];
    if (threadIdx.x < IDIM) xs[threadIdx.x] = x[t * IDIM + threadIdx.x];
    __syncthreads();
    for (int r = threadIdx.x; r < RDIM; r += blockDim.x) {
        const float4* w = (const float4*)(Win + r * IDIM);
        float4 a = __ldg(&w[0]), b = __ldg(&w[1]);
        g_u[t * RDIM + r] = a.x * xs[0] + a.y * xs[1] + a.z * xs[2] + a.w * xs[3]
                          + b.x * xs[4] + b.y * xs[5] + b.z * xs[6] + b.w * xs[7];
    }
}

// ---------------------------------------------------------------------------
// K2: per slot (one warp): compact 2 rows of W (zeros exact), then lane 0
// greedily assigns each entry a (sub-iter, lane) such that all 32 lanes of a
// sub-iter hit distinct smem banks. Lanes 0-15: row 2s; lanes 16-31: row 2s+1.
// ---------------------------------------------------------------------------
__global__ void k_prep(const float* __restrict__ W) {
    int wid  = threadIdx.x >> 5;
    int lane = threadIdx.x & 31;
    int slot = blockIdx.x * (blockDim.x / 32) + wid;
    if (slot >= NSLOT) return;

    Ent* ell = g_ellp + (size_t)slot * (NSUB_MAX * 32);

    // prefill padding: v=0, col=lane (conflict-free dummies)
    for (int idx = lane; idx < NSUB_MAX * 32; idx += 32)
        ell[idx] = Ent{0.0f, idx & 31};

    int cnts[2];
    for (int half = 0; half < 2; half++) {
        int row = 2 * slot + half;
        const float* wr = W + (size_t)row * RDIM;
        Ent* dst = g_rcomp + (size_t)row * MAXC;
        int cnt = 0;
        for (int c0 = 0; c0 < RDIM; c0 += 32) {
            float v = wr[c0 + lane];
            unsigned bal = __ballot_sync(0xffffffffu, v != 0.0f);
            if (v != 0.0f) {
                int pos = cnt + __popc(bal & ((1u << lane) - 1u));
                if (pos < MAXC) dst[pos] = Ent{v, c0 + lane};
            }
            cnt += __popc(bal);
        }
        cnts[half] = cnt < MAXC ? cnt : MAXC;
    }
    __syncwarp();

    __shared__ int s_mask[8][NSUB_MAX];
    __shared__ int s_cnt[8][2][NSUB_MAX];
    if (lane == 0) {
        int kmax = 0;
        for (int k = 0; k < NSUB_MAX; k++) {
            s_mask[wid][k] = 0;
            s_cnt[wid][0][k] = 0;
            s_cnt[wid][1][k] = 0;
        }
        for (int half = 0; half < 2; half++) {
            int row = 2 * slot + half;
            const Ent* src = g_rcomp + (size_t)row * MAXC;
            int base = 0;
            for (int i = 0; i < cnts[half]; i++) {
                Ent e = src[i];
                int b = e.c & 31;
                while (base < NSUB_MAX && s_cnt[wid][half][base] >= 16) base++;
                if (base >= NSUB_MAX) break;          // statistically never
                int k = -1;
                for (int kk = base; kk < NSUB_MAX; kk++) {
                    if (s_cnt[wid][half][kk] < 16 && !((s_mask[wid][kk] >> b) & 1)) {
                        k = kk; break;
                    }
                }
                if (k < 0) k = base;                   // accept rare conflict
                int j = s_cnt[wid][half][k];
                s_cnt[wid][half][k] = j + 1;
                s_mask[wid][k] |= 1 << b;
                if (k > kmax) kmax = k;
                ell[k * 32 + half * 16 + j] = e;
            }
        }
        g_np[slot] = kmax + 1;
    }
}

// ---------------------------------------------------------------------------
// K3: per-replay init
// ---------------------------------------------------------------------------
__global__ void k_init() {
    int i = blockIdx.x * blockDim.x + threadIdx.x;
    if (i < RDIM) g_hall[i] = 0.0f;            // h_0 = 0
    if (i < NBLK * CELL_STRIDE) g_arr[i] = 0u; // barrier cells
}

// ---------------------------------------------------------------------------
// K4 (launch #4 -> ncu target): persistent recurrence (R11 structure).
//   - W entries REGISTER-resident (36 vals + 18 packed byte-offset regs/lane).
//   - h_{t-1} fetched in FOUR 4 KB chunks by warps 0-3 (overlap with skew).
//   - Barrier de-hotspotted: ONE red.release per CTA (tid0, after tail
//     __syncthreads which orders all heads' stcg) into a cell padded to its
//     OWN 128B line -> barrier traffic spreads over ~128 L2 slices instead
//     of 4, and 4096 atomics/step collapse to 128.
// ---------------------------------------------------------------------------
__global__ void __launch_bounds__(NTHR, 1)
k_main() {
    __shared__ __align__(16) float sh[RDIM];          // 16 KB h
    __shared__ __align__(8) unsigned long long mbar[1];

    const int tid  = threadIdx.x;
    const int wid  = tid >> 5;
    const int lane = tid & 31;
    const int slot = blockIdx.x * SLOTS_PER_CTA + wid;
    const int half = lane >> 4;
    const int row  = 2 * slot + half;
    const bool head = (lane == 0) | (lane == 16);

    const uint32_t mbar_a = smem_u32(mbar);
    const uint32_t sh_a   = smem_u32(sh);

    if (tid == 0)
        asm volatile("mbarrier.init.shared.b64 [%0], 1;" :: "r"(mbar_a) : "memory");

    // one-time: load this lane's 36 entries into registers
    float    vv[NE];
    unsigned cp[NE / 2];   // two pre-scaled byte offsets per reg
    {
        const Ent* src = g_ellp + (size_t)slot * (NSUB_MAX * 32) + lane;
#pragma unroll
        for (int i = 0; i < NE; i += 2) {
            Ent e0 = src[i * 32];
            Ent e1 = src[(i + 1) * 32];
            vv[i]     = e0.v;
            vv[i + 1] = e1.v;
            cp[i >> 1] = ((unsigned)e0.c << 2) | ((unsigned)e1.c << 18);
        }
    }

    float u_next = head ? __ldg(&g_u[row]) : 0.0f;     // u for t=0
    __syncthreads();                                   // mbar init visible
    if (tid == 0) {
        asm volatile("fence.proxy.async;" ::: "memory");
        asm volatile("mbarrier.arrive.expect_tx.shared.b64 _, [%0], %1;"
                     :: "r"(mbar_a), "r"((unsigned)H_BYTES) : "memory");
    }
    __syncthreads();                                   // expect before any TMA

    for (int t = 0; t < TLEN; ++t) {
        // ---- warps 0-3: poll own CTA-group, then fetch its 4 KB chunk ----
        if (wid < NGRP) {
            if (t) {
                const unsigned tgt = (unsigned)t;      // single writer per cell
                const unsigned* cell =
                    &g_arr[(GRP_CTAS * wid + lane) * CELL_STRIDE];
                for (;;) {
                    unsigned v = ld_rlx(cell);
                    if (!__any_sync(0xffffffffu, v < tgt)) break;
                }
            }
            if (lane == 0) {
                const float* src = g_hall + (size_t)t * RDIM + wid * CHUNK_FLOATS;
                asm volatile(
                    "cp.async.bulk.shared::cluster.global.mbarrier::complete_tx::bytes "
                    "[%0], [%1], %2, [%3];"
                    :: "r"(sh_a + wid * CHUNK_BYTES), "l"(src),
                       "r"((unsigned)CHUNK_BYTES), "r"(mbar_a)
                    : "memory");
            }
        }
        // all threads wait until all 4 chunks landed (phase parity = t&1)
        {
            const unsigned par = (unsigned)(t & 1);
            unsigned done;
            asm volatile(
                "{\n\t.reg .pred p;\n\t"
                "mbarrier.try_wait.parity.acquire.cta.shared::cta.b64 p, [%1], %2;\n\t"
                "selp.b32 %0, 1, 0, p;\n\t}"
                : "=r"(done) : "r"(mbar_a), "r"(par) : "memory");
            if (!done) {
                asm volatile(
                    "{\n\t.reg .pred P1;\n\t"
                    "W%=:\n\t"
                    "mbarrier.try_wait.parity.acquire.cta.shared::cta.b64 P1, [%0], %1, 0x989680;\n\t"
                    "@P1 bra.uni D%=;\n\t"
                    "bra.uni W%=;\n\t"
                    "D%=:\n\t}"
                    :: "r"(mbar_a), "r"(par) : "memory");
            }
        }

        // ---- sparse dot: values/offsets from registers, gathers from smem ----
        const char* hb = (const char*)sh;
        float a0 = 0.0f, a1 = 0.0f;
#pragma unroll
        for (int i = 0; i < NE; i += 2) {
            unsigned p = cp[i >> 1];
            a0 += vv[i]     * *(const float*)(hb + (p & 0xFFFFu));
            a1 += vv[i + 1] * *(const float*)(hb + (p >> 16));
        }
        float acc = a0 + a1;
#pragma unroll
        for (int off = 8; off; off >>= 1)
            acc += __shfl_xor_sync(0xffffffffu, acc, off);

        if (head) {
            float hv = tanh_hw(acc + u_next);          // HW MUFU.TANH
            __stcg(g_hall + (size_t)(t + 1) * RDIM + row, hv);
            if (t + 1 < TLEN) u_next = __ldcg(&g_u[(size_t)(t + 1) * RDIM + row]);
        }
        // re-arm mbar for next step; must precede any warp's next-step TMA
        if (tid == 0 && t + 1 < TLEN) {
            asm volatile("fence.proxy.async;" ::: "memory");
            asm volatile("mbarrier.arrive.expect_tx.shared.b64 _, [%0], %1;"
                         :: "r"(mbar_a), "r"((unsigned)H_BYTES) : "memory");
        }
        // tail sync: orders all heads' stcg + all gathers + expect_tx before
        // the single release below AND protects sh reuse.
        __syncthreads();
        // arrive: ONE release per CTA; bar.sync established CTA-wide HB from
        // all heads' stores to this release.
        if (tid == 0) red_rel_add(&g_arr[blockIdx.x * CELL_STRIDE]);
    }
}

// ---------------------------------------------------------------------------
// K5: out[t][o] = bias[o] + sum_r h_{t+1}[r] * Wout[o][r]
// ---------------------------------------------------------------------------
__global__ void k_out(const float* __restrict__ Wout, const float* __restrict__ bias,
                      float* __restrict__ out) {
    int t = blockIdx.x;
    const float4* h4 = (const float4*)(g_hall + (size_t)(t + 1) * RDIM);
    float acc[ODIM];
#pragma unroll
    for (int o = 0; o < ODIM; o++) acc[o] = 0.0f;

    for (int r4 = threadIdx.x; r4 < RDIM / 4; r4 += blockDim.x) {
        float4 h = h4[r4];
#pragma unroll
        for (int o = 0; o < ODIM; o++) {
            float4 w = __ldg((const float4*)(Wout + o * RDIM) + r4);
            acc[o] += h.x * w.x + h.y * w.y + h.z * w.z + h.w * w.w;
        }
    }
    __shared__ float red[8][ODIM];
    int wid = threadIdx.x >> 5, lane = threadIdx.x & 31;
#pragma unroll
    for (int o = 0; o < ODIM; o++) {
        float v = acc[o];
#pragma unroll
        for (int off = 16; off; off >>= 1)
            v += __shfl_xor_sync(0xffffffffu, v, off);
        if (lane == 0) red[wid][o] = v;
    }
    __syncthreads();
    if (threadIdx.x < ODIM) {
        float s = bias[threadIdx.x];
#pragma unroll
        for (int w = 0; w < 8; w++) s += red[w][threadIdx.x];
        out[t * ODIM + threadIdx.x] = s;
    }
}

// ---------------------------------------------------------------------------
extern "C" void kernel_launch(void* const* d_in, const int* in_sizes, int n_in,
                              void* d_out, int out_size) {
    (void)in_sizes; (void)n_in; (void)out_size;
    const float* x      = (const float*)d_in[0];  // [1, 2048, 8]
    const float* Win    = (const float*)d_in[1];  // [4096, 8]
    const float* W      = (const float*)d_in[2];  // [4096, 4096]
    const float* Wout_w = (const float*)d_in[3];  // [8, 4096]
    const float* Wout_b = (const float*)d_in[4];  // [8]
    float* out = (float*)d_out;                   // [1, 2048, 8]

    k_u<<<TLEN, 256>>>(x, Win);                   // launch 1
    k_prep<<<NSLOT / 8, 256>>>(W);                // launch 2
    k_init<<<(RDIM + 255) / 256, 256>>>();        // launch 3
    k_main<<<NBLK, NTHR>>>();                     // launch 4 <- ncu target
    k_out<<<TLEN, 256>>>(Wout_w, Wout_b, out);    // launch 5
}

// round 14
// speedup vs baseline: 1.4331x; 1.2360x over previous
#include <cuda_runtime.h>
#include <cstdint>

// Problem constants (fixed by reference)
#define RDIM 4096
#define TLEN 2048
#define IDIM 8
#define ODIM 8
#define NBLK 128                 // persistent CTAs, co-resident on 148 SMs
#define NTHR 512                 // 16 warps
#define NSLOT (RDIM / 2)         // 2048 warp-slots (2 rows each, 16 lanes/row)
#define SLOTS_PER_CTA 16
#define MAXC 768                 // stage-1 compaction capacity (nnz ~410 +-20)
#define NSUB_MAX 36              // entries per lane: 16*36=576 nnz/row cap (+8.7 sd)
#define NE NSUB_MAX              // register-resident entries per lane
#define H_BYTES (RDIM * 4)       // 16 KB
#define NGRP 8                   // CTA groups / h chunks (2 KB each)
#define GRP_CTAS (NBLK / NGRP)   // 16 CTAs per group
#define CHUNK_BYTES (H_BYTES / NGRP)   // 2 KB
#define CHUNK_FLOATS (RDIM / NGRP)     // 512
#define CELL_STRIDE 32           // one 128B line per barrier cell (L2-slice spread)

struct __align__(8) Ent { float v; int c; };

// Scratch (device globals: no allocation allowed)
__device__ __align__(16) Ent g_ellp[NSLOT * NSUB_MAX * 32];  // ~19 MB packed ELL
__device__ Ent      g_rcomp[RDIM * MAXC];                    // stage-1 compaction
__device__ int      g_np[NSLOT];                             // sub-iters per slot
__device__ float    g_u[TLEN * RDIM];                        // Win @ x_t (32 MB)
__device__ __align__(16) float g_hall[(TLEN + 1) * RDIM];    // all hidden states
__device__ __align__(128) unsigned g_arr[NBLK * CELL_STRIDE]; // padded barrier cells

// STRONG scoped sync (guaranteed visibility; relaxed = no fence)
__device__ __forceinline__ unsigned ld_rlx(const unsigned* p) {
    unsigned v;
    asm volatile("ld.relaxed.gpu.global.u32 %0, [%1];" : "=r"(v) : "l"(p) : "memory");
    return v;
}
__device__ __forceinline__ void red_rel_add(unsigned* p) {
    asm volatile("red.release.gpu.global.add.u32 [%0], 1;" :: "l"(p) : "memory");
}
__device__ __forceinline__ uint32_t smem_u32(const void* p) {
    uint32_t a;
    asm("{ .reg .u64 t; cvta.to.shared.u64 t, %1; cvt.u32.u64 %0, t; }"
        : "=r"(a) : "l"(p));
    return a;
}
__device__ __forceinline__ float tanh_hw(float x) {
    float r;
    asm("tanh.approx.f32 %0, %1;" : "=f"(r) : "f"(x));
    return r;
}

// ---------------------------------------------------------------------------
// K1: u[t][r] = sum_i Win[r,i] * x[t,i]
// ---------------------------------------------------------------------------
__global__ void k_u(const float* __restrict__ x, const float* __restrict__ Win) {
    int t = blockIdx.x;
    __shared__ float xs[IDIM];
    if (threadIdx.x < IDIM) xs[threadIdx.x] = x[t * IDIM + threadIdx.x];
    __syncthreads();
    for (int r = threadIdx.x; r < RDIM; r += blockDim.x) {
        const float4* w = (const float4*)(Win + r * IDIM);
        float4 a = __ldg(&w[0]), b = __ldg(&w[1]);
        g_u[t * RDIM + r] = a.x * xs[0] + a.y * xs[1] + a.z * xs[2] + a.w * xs[3]
                          + b.x * xs[4] + b.y * xs[5] + b.z * xs[6] + b.w * xs[7];
    }
}

// ---------------------------------------------------------------------------
// K2: per slot (one warp): compact 2 rows of W (zeros exact), then lane 0
// greedily assigns each entry a (sub-iter, lane) such that all 32 lanes of a
// sub-iter hit distinct smem banks. Lanes 0-15: row 2s; lanes 16-31: row 2s+1.
// ---------------------------------------------------------------------------
__global__ void k_prep(const float* __restrict__ W) {
    int wid  = threadIdx.x >> 5;
    int lane = threadIdx.x & 31;
    int slot = blockIdx.x * (blockDim.x / 32) + wid;
    if (slot >= NSLOT) return;

    Ent* ell = g_ellp + (size_t)slot * (NSUB_MAX * 32);

    // prefill padding: v=0, col=lane (conflict-free dummies)
    for (int idx = lane; idx < NSUB_MAX * 32; idx += 32)
        ell[idx] = Ent{0.0f, idx & 31};

    int cnts[2];
    for (int half = 0; half < 2; half++) {
        int row = 2 * slot + half;
        const float* wr = W + (size_t)row * RDIM;
        Ent* dst = g_rcomp + (size_t)row * MAXC;
        int cnt = 0;
        for (int c0 = 0; c0 < RDIM; c0 += 32) {
            float v = wr[c0 + lane];
            unsigned bal = __ballot_sync(0xffffffffu, v != 0.0f);
            if (v != 0.0f) {
                int pos = cnt + __popc(bal & ((1u << lane) - 1u));
                if (pos < MAXC) dst[pos] = Ent{v, c0 + lane};
            }
            cnt += __popc(bal);
        }
        cnts[half] = cnt < MAXC ? cnt : MAXC;
    }
    __syncwarp();

    __shared__ int s_mask[8][NSUB_MAX];
    __shared__ int s_cnt[8][2][NSUB_MAX];
    if (lane == 0) {
        int kmax = 0;
        for (int k = 0; k < NSUB_MAX; k++) {
            s_mask[wid][k] = 0;
            s_cnt[wid][0][k] = 0;
            s_cnt[wid][1][k] = 0;
        }
        for (int half = 0; half < 2; half++) {
            int row = 2 * slot + half;
            const Ent* src = g_rcomp + (size_t)row * MAXC;
            int base = 0;
            for (int i = 0; i < cnts[half]; i++) {
                Ent e = src[i];
                int b = e.c & 31;
                while (base < NSUB_MAX && s_cnt[wid][half][base] >= 16) base++;
                if (base >= NSUB_MAX) break;          // statistically never
                int k = -1;
                for (int kk = base; kk < NSUB_MAX; kk++) {
                    if (s_cnt[wid][half][kk] < 16 && !((s_mask[wid][kk] >> b) & 1)) {
                        k = kk; break;
                    }
                }
                if (k < 0) k = base;                   // accept rare conflict
                int j = s_cnt[wid][half][k];
                s_cnt[wid][half][k] = j + 1;
                s_mask[wid][k] |= 1 << b;
                if (k > kmax) kmax = k;
                ell[k * 32 + half * 16 + j] = e;
            }
        }
        g_np[slot] = kmax + 1;
    }
}

// ---------------------------------------------------------------------------
// K3: per-replay init
// ---------------------------------------------------------------------------
__global__ void k_init() {
    int i = blockIdx.x * blockDim.x + threadIdx.x;
    if (i < RDIM) g_hall[i] = 0.0f;            // h_0 = 0
    if (i < NBLK * CELL_STRIDE) g_arr[i] = 0u; // barrier cells
}

// ---------------------------------------------------------------------------
// K4 (launch #4 -> ncu target): persistent recurrence (Round-11 structure).
//   - W entries REGISTER-resident (36 vals + 18 packed byte-offset regs/lane).
//   - h_{t-1} fetched in EIGHT 2 KB chunks: warp w (w<8) polls CTA group w
//     (16 cells, lanes mirrored) and issues its chunk's TMA on completion
//     -> post-last-arrival path = detect + 2 KB only; finer skew overlap.
//   - Heads release IMMEDIATELY after their stcg (32/CTA, target 32t):
//     proven critical (R10/R12/R13 all regressed by delaying release).
//   - Barrier cells padded to one 128B line each (L2-slice spread).
// ---------------------------------------------------------------------------
__global__ void __launch_bounds__(NTHR, 1)
k_main() {
    __shared__ __align__(16) float sh[RDIM];          // 16 KB h
    __shared__ __align__(8) unsigned long long mbar[1];

    const int tid  = threadIdx.x;
    const int wid  = tid >> 5;
    const int lane = tid & 31;
    const int slot = blockIdx.x * SLOTS_PER_CTA + wid;
    const int half = lane >> 4;
    const int row  = 2 * slot + half;
    const bool head = (lane == 0) | (lane == 16);

    const uint32_t mbar_a = smem_u32(mbar);
    const uint32_t sh_a   = smem_u32(sh);

    if (tid == 0)
        asm volatile("mbarrier.init.shared.b64 [%0], 1;" :: "r"(mbar_a) : "memory");

    // one-time: load this lane's 36 entries into registers
    float    vv[NE];
    unsigned cp[NE / 2];   // two pre-scaled byte offsets per reg
    {
        const Ent* src = g_ellp + (size_t)slot * (NSUB_MAX * 32) + lane;
#pragma unroll
        for (int i = 0; i < NE; i += 2) {
            Ent e0 = src[i * 32];
            Ent e1 = src[(i + 1) * 32];
            vv[i]     = e0.v;
            vv[i + 1] = e1.v;
            cp[i >> 1] = ((unsigned)e0.c << 2) | ((unsigned)e1.c << 18);
        }
    }

    float u_next = head ? __ldg(&g_u[row]) : 0.0f;     // u for t=0
    __syncthreads();                                   // mbar init visible
    if (tid == 0) {
        asm volatile("fence.proxy.async;" ::: "memory");
        asm volatile("mbarrier.arrive.expect_tx.shared.b64 _, [%0], %1;"
                     :: "r"(mbar_a), "r"((unsigned)H_BYTES) : "memory");
    }
    __syncthreads();                                   // expect before any TMA

    for (int t = 0; t < TLEN; ++t) {
        // ---- warps 0-7: poll own 16-CTA group, then fetch its 2 KB chunk ----
        if (wid < NGRP) {
            if (t) {
                const unsigned tgt = 32u * (unsigned)t;
                const unsigned* cell =
                    &g_arr[(GRP_CTAS * wid + (lane & 15)) * CELL_STRIDE];
                for (;;) {
                    unsigned v = ld_rlx(cell);
                    if (!__any_sync(0xffffffffu, v < tgt)) break;
                }
            }
            if (lane == 0) {
                const float* src = g_hall + (size_t)t * RDIM + wid * CHUNK_FLOATS;
                asm volatile(
                    "cp.async.bulk.shared::cluster.global.mbarrier::complete_tx::bytes "
                    "[%0], [%1], %2, [%3];"
                    :: "r"(sh_a + wid * CHUNK_BYTES), "l"(src),
                       "r"((unsigned)CHUNK_BYTES), "r"(mbar_a)
                    : "memory");
            }
        }
        // all threads wait until all 8 chunks landed (phase parity = t&1)
        {
            const unsigned par = (unsigned)(t & 1);
            unsigned done;
            asm volatile(
                "{\n\t.reg .pred p;\n\t"
                "mbarrier.try_wait.parity.acquire.cta.shared::cta.b64 p, [%1], %2;\n\t"
                "selp.b32 %0, 1, 0, p;\n\t}"
                : "=r"(done) : "r"(mbar_a), "r"(par) : "memory");
            if (!done) {
                asm volatile(
                    "{\n\t.reg .pred P1;\n\t"
                    "W%=:\n\t"
                    "mbarrier.try_wait.parity.acquire.cta.shared::cta.b64 P1, [%0], %1, 0x989680;\n\t"
                    "@P1 bra.uni D%=;\n\t"
                    "bra.uni W%=;\n\t"
                    "D%=:\n\t}"
                    :: "r"(mbar_a), "r"(par) : "memory");
            }
        }

        // ---- sparse dot: values/offsets from registers, gathers from smem ----
        const char* hb = (const char*)sh;
        float a0 = 0.0f, a1 = 0.0f;
#pragma unroll
        for (int i = 0; i < NE; i += 2) {
            unsigned p = cp[i >> 1];
            a0 += vv[i]     * *(const float*)(hb + (p & 0xFFFFu));
            a1 += vv[i + 1] * *(const float*)(hb + (p >> 16));
        }
        float acc = a0 + a1;
#pragma unroll
        for (int off = 8; off; off >>= 1)
            acc += __shfl_xor_sync(0xffffffffu, acc, off);

        if (head) {
            float hv = tanh_hw(acc + u_next);          // HW MUFU.TANH
            __stcg(g_hall + (size_t)(t + 1) * RDIM + row, hv);
            // arrive IMMEDIATELY: release covers own h store
            red_rel_add(&g_arr[blockIdx.x * CELL_STRIDE]);
            if (t + 1 < TLEN) u_next = __ldcg(&g_u[(size_t)(t + 1) * RDIM + row]);
        }
        // re-arm mbar for next step; must precede any warp's next-step TMA
        if (tid == 0 && t + 1 < TLEN) {
            asm volatile("fence.proxy.async;" ::: "memory");
            asm volatile("mbarrier.arrive.expect_tx.shared.b64 _, [%0], %1;"
                         :: "r"(mbar_a), "r"((unsigned)H_BYTES) : "memory");
        }
        // tail sync: orders expect_tx before next TMAs and protects sh reuse
        __syncthreads();
    }
}

// ---------------------------------------------------------------------------
// K5: out[t][o] = bias[o] + sum_r h_{t+1}[r] * Wout[o][r]
// ---------------------------------------------------------------------------
__global__ void k_out(const float* __restrict__ Wout, const float* __restrict__ bias,
                      float* __restrict__ out) {
    int t = blockIdx.x;
    const float4* h4 = (const float4*)(g_hall + (size_t)(t + 1) * RDIM);
    float acc[ODIM];
#pragma unroll
    for (int o = 0; o < ODIM; o++) acc[o] = 0.0f;

    for (int r4 = threadIdx.x; r4 < RDIM / 4; r4 += blockDim.x) {
        float4 h = h4[r4];
#pragma unroll
        for (int o = 0; o < ODIM; o++) {
            float4 w = __ldg((const float4*)(Wout + o * RDIM) + r4);
            acc[o] += h.x * w.x + h.y * w.y + h.z * w.z + h.w * w.w;
        }
    }
    __shared__ float red[8][ODIM];
    int wid = threadIdx.x >> 5, lane = threadIdx.x & 31;
#pragma unroll
    for (int o = 0; o < ODIM; o++) {
        float v = acc[o];
#pragma unroll
        for (int off = 16; off; off >>= 1)
            v += __shfl_xor_sync(0xffffffffu, v, off);
        if (lane == 0) red[wid][o] = v;
    }
    __syncthreads();
    if (threadIdx.x < ODIM) {
        float s = bias[threadIdx.x];
#pragma unroll
        for (int w = 0; w < 8; w++) s += red[w][threadIdx.x];
        out[t * ODIM + threadIdx.x] = s;
    }
}

// ---------------------------------------------------------------------------
extern "C" void kernel_launch(void* const* d_in, const int* in_sizes, int n_in,
                              void* d_out, int out_size) {
    (void)in_sizes; (void)n_in; (void)out_size;
    const float* x      = (const float*)d_in[0];  // [1, 2048, 8]
    const float* Win    = (const float*)d_in[1];  // [4096, 8]
    const float* W      = (const float*)d_in[2];  // [4096, 4096]
    const float* Wout_w = (const float*)d_in[3];  // [8, 4096]
    const float* Wout_b = (const float*)d_in[4];  // [8]
    float* out = (float*)d_out;                   // [1, 2048, 8]

    k_u<<<TLEN, 256>>>(x, Win);                   // launch 1
    k_prep<<<NSLOT / 8, 256>>>(W);                // launch 2
    k_init<<<(NBLK * CELL_STRIDE + 4095) / 256 + 16, 256>>>();  // launch 3
    k_main<<<NBLK, NTHR>>>();                     // launch 4 <- ncu target
    k_out<<<TLEN, 256>>>(Wout_w, Wout_b, out);    // launch 5
}

// round 15
// speedup vs baseline: 1.4372x; 1.0029x over previous
#include <cuda_runtime.h>
#include <cstdint>

// Problem constants (fixed by reference)
#define RDIM 4096
#define TLEN 2048
#define IDIM 8
#define ODIM 8
#define NBLK 128                 // persistent CTAs, co-resident on 148 SMs
#define NTHR 512                 // 16 warps
#define NSLOT (RDIM / 2)         // 2048 warp-slots (2 rows each, 16 lanes/row)
#define SLOTS_PER_CTA 16
#define MAXC 768                 // stage-1 compaction capacity (nnz ~410 +-20)
#define NSUB_MAX 36              // 2 windows x 18 sub-iters (per column half)
#define NWIN 18                  // sub-iters per column-half window
#define NE NSUB_MAX              // register-resident entries per lane
#define H_BYTES (RDIM * 4)       // 16 KB
#define HALF_BYTES (H_BYTES / 2) // 8 KB per column half
#define NGRP 16                  // CTA groups / h chunks (1 KB each)
#define GRP_CTAS (NBLK / NGRP)   // 8 CTAs per group
#define CHUNK_BYTES (H_BYTES / NGRP)   // 1 KB
#define CHUNK_FLOATS (RDIM / NGRP)     // 256
#define CELL_STRIDE 32           // one 128B line per barrier cell (L2-slice spread)

struct __align__(8) Ent { float v; int c; };

// Scratch (device globals: no allocation allowed)
__device__ __align__(16) Ent g_ellp[NSLOT * NSUB_MAX * 32];  // ~19 MB packed ELL
__device__ Ent      g_rcomp[RDIM * MAXC];                    // stage-1 compaction
__device__ int      g_np[NSLOT];                             // sub-iters per slot
__device__ float    g_u[TLEN * RDIM];                        // Win @ x_t (32 MB)
__device__ __align__(16) float g_hall[(TLEN + 1) * RDIM];    // all hidden states
__device__ __align__(128) unsigned g_arr[NBLK * CELL_STRIDE]; // padded barrier cells

// STRONG scoped sync (guaranteed visibility; relaxed = no fence)
__device__ __forceinline__ unsigned ld_rlx(const unsigned* p) {
    unsigned v;
    asm volatile("ld.relaxed.gpu.global.u32 %0, [%1];" : "=r"(v) : "l"(p) : "memory");
    return v;
}
__device__ __forceinline__ void red_rel_add(unsigned* p) {
    asm volatile("red.release.gpu.global.add.u32 [%0], 1;" :: "l"(p) : "memory");
}
__device__ __forceinline__ uint32_t smem_u32(const void* p) {
    uint32_t a;
    asm("{ .reg .u64 t; cvta.to.shared.u64 t, %1; cvt.u32.u64 %0, t; }"
        : "=r"(a) : "l"(p));
    return a;
}
__device__ __forceinline__ float tanh_hw(float x) {
    float r;
    asm("tanh.approx.f32 %0, %1;" : "=f"(r) : "f"(x));
    return r;
}
__device__ __forceinline__ void mbar_wait(uint32_t mb, unsigned par) {
    unsigned done;
    asm volatile(
        "{\n\t.reg .pred p;\n\t"
        "mbarrier.try_wait.parity.acquire.cta.shared::cta.b64 p, [%1], %2;\n\t"
        "selp.b32 %0, 1, 0, p;\n\t}"
        : "=r"(done) : "r"(mb), "r"(par) : "memory");
    if (!done) {
        asm volatile(
            "{\n\t.reg .pred P1;\n\t"
            "W%=:\n\t"
            "mbarrier.try_wait.parity.acquire.cta.shared::cta.b64 P1, [%0], %1, 0x989680;\n\t"
            "@P1 bra.uni D%=;\n\t"
            "bra.uni W%=;\n\t"
            "D%=:\n\t}"
            :: "r"(mb), "r"(par) : "memory");
    }
}

// ---------------------------------------------------------------------------
// K1: u[t][r] = sum_i Win[r,i] * x[t,i]
// ---------------------------------------------------------------------------
__global__ void k_u(const float* __restrict__ x, const float* __restrict__ Win) {
    int t = blockIdx.x;
    __shared__ float xs[IDIM];
    if (threadIdx.x < IDIM) xs[threadIdx.x] = x[t * IDIM + threadIdx.x];
    __syncthreads();
    for (int r = threadIdx.x; r < RDIM; r += blockDim.x) {
        const float4* w = (const float4*)(Win + r * IDIM);
        float4 a = __ldg(&w[0]), b = __ldg(&w[1]);
        g_u[t * RDIM + r] = a.x * xs[0] + a.y * xs[1] + a.z * xs[2] + a.w * xs[3]
                          + b.x * xs[4] + b.y * xs[5] + b.z * xs[6] + b.w * xs[7];
    }
}

// ---------------------------------------------------------------------------
// K2: per slot (one warp): compact 2 rows of W (zeros exact), then lane 0
// schedules each entry into a (sub-iter, lane) slot with a free smem bank.
// NEW: entries are windowed by COLUMN HALF -> sub-iters [0,18) hold columns
// <2048, sub-iters [18,36) hold columns >=2048, enabling phase-split gather.
// Lanes 0-15 serve row 2s; lanes 16-31 serve row 2s+1.
// ---------------------------------------------------------------------------
__global__ void k_prep(const float* __restrict__ W) {
    int wid  = threadIdx.x >> 5;
    int lane = threadIdx.x & 31;
    int slot = blockIdx.x * (blockDim.x / 32) + wid;
    if (slot >= NSLOT) return;

    Ent* ell = g_ellp + (size_t)slot * (NSUB_MAX * 32);

    // prefill padding: v=0, col=lane for window 0 / 2048+lane for window 1
    for (int idx = lane; idx < NSUB_MAX * 32; idx += 32) {
        int k = idx / 32;
        int base_col = (k < NWIN) ? 0 : 2048;
        ell[idx] = Ent{0.0f, base_col + (idx & 31)};
    }

    int cnts[2];
    for (int rh = 0; rh < 2; rh++) {
        int row = 2 * slot + rh;
        const float* wr = W + (size_t)row * RDIM;
        Ent* dst = g_rcomp + (size_t)row * MAXC;
        int cnt = 0;
        for (int c0 = 0; c0 < RDIM; c0 += 32) {
            float v = wr[c0 + lane];
            unsigned bal = __ballot_sync(0xffffffffu, v != 0.0f);
            if (v != 0.0f) {
                int pos = cnt + __popc(bal & ((1u << lane) - 1u));
                if (pos < MAXC) dst[pos] = Ent{v, c0 + lane};
            }
            cnt += __popc(bal);
        }
        cnts[rh] = cnt < MAXC ? cnt : MAXC;
    }
    __syncwarp();

    __shared__ int s_mask[8][NSUB_MAX];    // occupied banks per sub-iter
    __shared__ int s_cnt[8][2][NSUB_MAX];  // filled lanes per row-half per sub-iter
    if (lane == 0) {
        for (int k = 0; k < NSUB_MAX; k++) {
            s_mask[wid][k] = 0;
            s_cnt[wid][0][k] = 0;
            s_cnt[wid][1][k] = 0;
        }
        for (int rh = 0; rh < 2; rh++) {
            int row = 2 * slot + rh;
            const Ent* src = g_rcomp + (size_t)row * MAXC;
            int base[2] = {0, NWIN};            // search start per column half
            for (int i = 0; i < cnts[rh]; i++) {
                Ent e = src[i];
                int ch  = (e.c >= 2048);        // column half -> window
                int b   = e.c & 31;
                int wlo = ch * NWIN, whi = wlo + NWIN;
                while (base[ch] < whi && s_cnt[wid][rh][base[ch]] >= 16) base[ch]++;
                if (base[ch] >= whi) continue;  // window full: statistically never
                int k = -1;
                for (int kk = base[ch]; kk < whi; kk++) {
                    if (s_cnt[wid][rh][kk] < 16 && !((s_mask[wid][kk] >> b) & 1)) {
                        k = kk; break;
                    }
                }
                if (k < 0) k = base[ch];        // accept rare conflict
                int j = s_cnt[wid][rh][k];
                s_cnt[wid][rh][k] = j + 1;
                s_mask[wid][k] |= 1 << b;
                ell[k * 32 + rh * 16 + j] = e;
            }
        }
        g_np[slot] = NSUB_MAX;
    }
}

// ---------------------------------------------------------------------------
// K3: per-replay init
// ---------------------------------------------------------------------------
__global__ void k_init() {
    int i = blockIdx.x * blockDim.x + threadIdx.x;
    if (i < RDIM) g_hall[i] = 0.0f;            // h_0 = 0
    if (i < NBLK * CELL_STRIDE) g_arr[i] = 0u; // barrier cells
}

// ---------------------------------------------------------------------------
// K4 (launch #4 -> ncu target): persistent recurrence, phase-split gather.
//   - W entries REGISTER-resident, windowed by column half.
//   - h_{t-1} fetched in SIXTEEN 1 KB chunks: warp w polls its 8-CTA group
//     (lanes 0-7) then fetches chunk w. Chunks 0-7 (rows <2048) complete
//     mbar0; chunks 8-15 complete mbar1.
//   - Gather phase 0 starts as soon as half 0 landed, overlapping half 1's
//     arrival -> post-last-arrival exposed work halves (18 iters + 1KB TMA).
//   - Heads release IMMEDIATELY after stcg (proven critical R10/12/13).
// ---------------------------------------------------------------------------
__global__ void __launch_bounds__(NTHR, 1)
k_main() {
    __shared__ __align__(16) float sh[RDIM];          // 16 KB h
    __shared__ __align__(8) unsigned long long mbar[2];

    const int tid  = threadIdx.x;
    const int wid  = tid >> 5;
    const int lane = tid & 31;
    const int slot = blockIdx.x * SLOTS_PER_CTA + wid;
    const int half = lane >> 4;
    const int row  = 2 * slot + half;
    const bool head = (lane == 0) | (lane == 16);

    const uint32_t mbar0_a = smem_u32(&mbar[0]);
    const uint32_t mbar1_a = smem_u32(&mbar[1]);
    const uint32_t sh_a    = smem_u32(sh);

    if (tid == 0) {
        asm volatile("mbarrier.init.shared.b64 [%0], 1;" :: "r"(mbar0_a) : "memory");
        asm volatile("mbarrier.init.shared.b64 [%0], 1;" :: "r"(mbar1_a) : "memory");
    }

    // one-time: load this lane's 36 entries into registers
    float    vv[NE];
    unsigned cp[NE / 2];   // two pre-scaled byte offsets per reg
    {
        const Ent* src = g_ellp + (size_t)slot * (NSUB_MAX * 32) + lane;
#pragma unroll
        for (int i = 0; i < NE; i += 2) {
            Ent e0 = src[i * 32];
            Ent e1 = src[(i + 1) * 32];
            vv[i]     = e0.v;
            vv[i + 1] = e1.v;
            cp[i >> 1] = ((unsigned)e0.c << 2) | ((unsigned)e1.c << 18);
        }
    }

    float u_next = head ? __ldg(&g_u[row]) : 0.0f;     // u for t=0
    __syncthreads();                                   // mbar init visible
    if (tid == 0) {
        asm volatile("fence.proxy.async;" ::: "memory");
        asm volatile("mbarrier.arrive.expect_tx.shared.b64 _, [%0], %1;"
                     :: "r"(mbar0_a), "r"((unsigned)HALF_BYTES) : "memory");
        asm volatile("mbarrier.arrive.expect_tx.shared.b64 _, [%0], %1;"
                     :: "r"(mbar1_a), "r"((unsigned)HALF_BYTES) : "memory");
    }
    __syncthreads();                                   // expects before any TMA

    const char* hb = (const char*)sh;

    for (int t = 0; t < TLEN; ++t) {
        const unsigned par = (unsigned)(t & 1);

        // ---- every warp: poll own 8-CTA group, then fetch its 1 KB chunk ----
        {
            if (t) {
                const unsigned tgt = 32u * (unsigned)t;
                const unsigned* cell =
                    &g_arr[(GRP_CTAS * wid + (lane & 7)) * CELL_STRIDE];
                for (;;) {
                    unsigned v = ld_rlx(cell);
                    if (!__any_sync(0xffffffffu, v < tgt)) break;
                }
            }
            if (lane == 0) {
                const uint32_t mb = (wid < 8) ? mbar0_a : mbar1_a;
                const float* src = g_hall + (size_t)t * RDIM + wid * CHUNK_FLOATS;
                asm volatile(
                    "cp.async.bulk.shared::cluster.global.mbarrier::complete_tx::bytes "
                    "[%0], [%1], %2, [%3];"
                    :: "r"(sh_a + wid * CHUNK_BYTES), "l"(src),
                       "r"((unsigned)CHUNK_BYTES), "r"(mb)
                    : "memory");
            }
        }

        // ---- phase 0: wait half 0 (cols < 2048), gather window 0 ----
        mbar_wait(mbar0_a, par);
        float a0 = 0.0f, a1 = 0.0f;
#pragma unroll
        for (int i = 0; i < NWIN; i += 2) {
            unsigned p = cp[i >> 1];
            a0 += vv[i]     * *(const float*)(hb + (p & 0xFFFFu));
            a1 += vv[i + 1] * *(const float*)(hb + (p >> 16));
        }

        // ---- phase 1: wait half 1 (cols >= 2048), gather window 1 ----
        mbar_wait(mbar1_a, par);
#pragma unroll
        for (int i = NWIN; i < NE; i += 2) {
            unsigned p = cp[i >> 1];
            a0 += vv[i]     * *(const float*)(hb + (p & 0xFFFFu));
            a1 += vv[i + 1] * *(const float*)(hb + (p >> 16));
        }
        float acc = a0 + a1;
#pragma unroll
        for (int off = 8; off; off >>= 1)
            acc += __shfl_xor_sync(0xffffffffu, acc, off);

        if (head) {
            float hv = tanh_hw(acc + u_next);          // HW MUFU.TANH
            __stcg(g_hall + (size_t)(t + 1) * RDIM + row, hv);
            // arrive IMMEDIATELY: release covers own h store
            red_rel_add(&g_arr[blockIdx.x * CELL_STRIDE]);
            if (t + 1 < TLEN) u_next = __ldcg(&g_u[(size_t)(t + 1) * RDIM + row]);
        }
        // re-arm both mbars for next step; must precede any next-step TMA
        if (tid == 0 && t + 1 < TLEN) {
            asm volatile("fence.proxy.async;" ::: "memory");
            asm volatile("mbarrier.arrive.expect_tx.shared.b64 _, [%0], %1;"
                         :: "r"(mbar0_a), "r"((unsigned)HALF_BYTES) : "memory");
            asm volatile("mbarrier.arrive.expect_tx.shared.b64 _, [%0], %1;"
                         :: "r"(mbar1_a), "r"((unsigned)HALF_BYTES) : "memory");
        }
        // tail sync: orders expects before next TMAs and protects sh reuse
        __syncthreads();
    }
}

// ---------------------------------------------------------------------------
// K5: out[t][o] = bias[o] + sum_r h_{t+1}[r] * Wout[o][r]
// ---------------------------------------------------------------------------
__global__ void k_out(const float* __restrict__ Wout, const float* __restrict__ bias,
                      float* __restrict__ out) {
    int t = blockIdx.x;
    const float4* h4 = (const float4*)(g_hall + (size_t)(t + 1) * RDIM);
    float acc[ODIM];
#pragma unroll
    for (int o = 0; o < ODIM; o++) acc[o] = 0.0f;

    for (int r4 = threadIdx.x; r4 < RDIM / 4; r4 += blockDim.x) {
        float4 h = h4[r4];
#pragma unroll
        for (int o = 0; o < ODIM; o++) {
            float4 w = __ldg((const float4*)(Wout + o * RDIM) + r4);
            acc[o] += h.x * w.x + h.y * w.y + h.z * w.z + h.w * w.w;
        }
    }
    __shared__ float red[8][ODIM];
    int wid = threadIdx.x >> 5, lane = threadIdx.x & 31;
#pragma unroll
    for (int o = 0; o < ODIM; o++) {
        float v = acc[o];
#pragma unroll
        for (int off = 16; off; off >>= 1)
            v += __shfl_xor_sync(0xffffffffu, v, off);
        if (lane == 0) red[wid][o] = v;
    }
    __syncthreads();
    if (threadIdx.x < ODIM) {
        float s = bias[threadIdx.x];
#pragma unroll
        for (int w = 0; w < 8; w++) s += red[w][threadIdx.x];
        out[t * ODIM + threadIdx.x] = s;
    }
}

// ---------------------------------------------------------------------------
extern "C" void kernel_launch(void* const* d_in, const int* in_sizes, int n_in,
                              void* d_out, int out_size) {
    (void)in_sizes; (void)n_in; (void)out_size;
    const float* x      = (const float*)d_in[0];  // [1, 2048, 8]
    const float* Win    = (const float*)d_in[1];  // [4096, 8]
    const float* W      = (const float*)d_in[2];  // [4096, 4096]
    const float* Wout_w = (const float*)d_in[3];  // [8, 4096]
    const float* Wout_b = (const float*)d_in[4];  // [8]
    float* out = (float*)d_out;                   // [1, 2048, 8]

    k_u<<<TLEN, 256>>>(x, Win);                   // launch 1
    k_prep<<<NSLOT / 8, 256>>>(W);                // launch 2
    k_init<<<(NBLK * CELL_STRIDE + 4095) / 256 + 16, 256>>>();  // launch 3
    k_main<<<NBLK, NTHR>>>();                     // launch 4 <- ncu target
    k_out<<<TLEN, 256>>>(Wout_w, Wout_b, out);    // launch 5
}

// round 16
// speedup vs baseline: 1.6942x; 1.1789x over previous
#include <cuda_runtime.h>
#include <cstdint>

// Problem constants (fixed by reference)
#define RDIM 4096
#define TLEN 2048
#define IDIM 8
#define ODIM 8
#define NBLK 128                 // persistent CTAs, co-resident on 148 SMs
#define NTHR 512                 // 16 warps
#define NSLOT (RDIM / 2)         // 2048 warp-slots (2 rows each, 16 lanes/row)
#define SLOTS_PER_CTA 16
#define MAXC 768                 // stage-1 compaction capacity (nnz ~410 +-20)
#define NSUB_MAX 36              // 2 windows x 18 sub-iters (per column half)
#define NWIN 18                  // sub-iters per column-half window
#define NE NSUB_MAX              // register-resident entries per lane

struct __align__(8) Ent { float v; int c; };

// Scratch (device globals: no allocation allowed)
__device__ __align__(16) Ent g_ellp[NSLOT * NSUB_MAX * 32];  // ~19 MB packed ELL
__device__ Ent      g_rcomp[RDIM * MAXC];                    // stage-1 compaction
__device__ int      g_np[NSLOT];                             // sub-iters per slot
__device__ float    g_u[TLEN * RDIM];                        // Win @ x_t (32 MB)
__device__ __align__(16) float g_hall[(TLEN + 1) * RDIM];    // all hidden states
// tagged ping-pong h: high 32 bits = step tag, low 32 bits = float value
__device__ __align__(16) unsigned long long g_hb[2][RDIM];

// STRONG relaxed (coherent, fence-free) 64-bit ops — detection == data fetch
__device__ __forceinline__ unsigned long long ld_rlx64(const unsigned long long* p) {
    unsigned long long v;
    asm volatile("ld.relaxed.gpu.global.u64 %0, [%1];" : "=l"(v) : "l"(p) : "memory");
    return v;
}
__device__ __forceinline__ void st_rlx64(unsigned long long* p, unsigned long long v) {
    asm volatile("st.relaxed.gpu.global.u64 [%0], %1;" :: "l"(p), "l"(v) : "memory");
}
__device__ __forceinline__ float tanh_hw(float x) {
    float r;
    asm("tanh.approx.f32 %0, %1;" : "=f"(r) : "f"(x));
    return r;
}

// ---------------------------------------------------------------------------
// K1: u[t][r] = sum_i Win[r,i] * x[t,i]
// ---------------------------------------------------------------------------
__global__ void k_u(const float* __restrict__ x, const float* __restrict__ Win) {
    int t = blockIdx.x;
    __shared__ float xs[IDIM];
    if (threadIdx.x < IDIM) xs[threadIdx.x] = x[t * IDIM + threadIdx.x];
    __syncthreads();
    for (int r = threadIdx.x; r < RDIM; r += blockDim.x) {
        const float4* w = (const float4*)(Win + r * IDIM);
        float4 a = __ldg(&w[0]), b = __ldg(&w[1]);
        g_u[t * RDIM + r] = a.x * xs[0] + a.y * xs[1] + a.z * xs[2] + a.w * xs[3]
                          + b.x * xs[4] + b.y * xs[5] + b.z * xs[6] + b.w * xs[7];
    }
}

// ---------------------------------------------------------------------------
// K2: per slot (one warp): compact 2 rows of W (zeros exact), then lane 0
// schedules each entry into a (sub-iter, lane) slot with a free smem bank
// (windowed by column half; windowing retained from R15, harmless).
// Lanes 0-15 serve row 2s; lanes 16-31 serve row 2s+1.
// ---------------------------------------------------------------------------
__global__ void k_prep(const float* __restrict__ W) {
    int wid  = threadIdx.x >> 5;
    int lane = threadIdx.x & 31;
    int slot = blockIdx.x * (blockDim.x / 32) + wid;
    if (slot >= NSLOT) return;

    Ent* ell = g_ellp + (size_t)slot * (NSUB_MAX * 32);

    // prefill padding: v=0, col=lane for window 0 / 2048+lane for window 1
    for (int idx = lane; idx < NSUB_MAX * 32; idx += 32) {
        int k = idx / 32;
        int base_col = (k < NWIN) ? 0 : 2048;
        ell[idx] = Ent{0.0f, base_col + (idx & 31)};
    }

    int cnts[2];
    for (int rh = 0; rh < 2; rh++) {
        int row = 2 * slot + rh;
        const float* wr = W + (size_t)row * RDIM;
        Ent* dst = g_rcomp + (size_t)row * MAXC;
        int cnt = 0;
        for (int c0 = 0; c0 < RDIM; c0 += 32) {
            float v = wr[c0 + lane];
            unsigned bal = __ballot_sync(0xffffffffu, v != 0.0f);
            if (v != 0.0f) {
                int pos = cnt + __popc(bal & ((1u << lane) - 1u));
                if (pos < MAXC) dst[pos] = Ent{v, c0 + lane};
            }
            cnt += __popc(bal);
        }
        cnts[rh] = cnt < MAXC ? cnt : MAXC;
    }
    __syncwarp();

    __shared__ int s_mask[8][NSUB_MAX];    // occupied banks per sub-iter
    __shared__ int s_cnt[8][2][NSUB_MAX];  // filled lanes per row-half per sub-iter
    if (lane == 0) {
        for (int k = 0; k < NSUB_MAX; k++) {
            s_mask[wid][k] = 0;
            s_cnt[wid][0][k] = 0;
            s_cnt[wid][1][k] = 0;
        }
        for (int rh = 0; rh < 2; rh++) {
            int row = 2 * slot + rh;
            const Ent* src = g_rcomp + (size_t)row * MAXC;
            int base[2] = {0, NWIN};            // search start per column half
            for (int i = 0; i < cnts[rh]; i++) {
                Ent e = src[i];
                int ch  = (e.c >= 2048);        // column half -> window
                int b   = e.c & 31;
                int wlo = ch * NWIN, whi = wlo + NWIN;
                while (base[ch] < whi && s_cnt[wid][rh][base[ch]] >= 16) base[ch]++;
                if (base[ch] >= whi) continue;  // window full: statistically never
                int k = -1;
                for (int kk = base[ch]; kk < whi; kk++) {
                    if (s_cnt[wid][rh][kk] < 16 && !((s_mask[wid][kk] >> b) & 1)) {
                        k = kk; break;
                    }
                }
                if (k < 0) k = base[ch];        // accept rare conflict
                int j = s_cnt[wid][rh][k];
                s_cnt[wid][rh][k] = j + 1;
                s_mask[wid][k] |= 1 << b;
                ell[k * 32 + rh * 16 + j] = e;
            }
        }
        g_np[slot] = NSUB_MAX;
    }
}

// ---------------------------------------------------------------------------
// K3: per-replay init. h_0 = 0 tagged 0 in buf0; buf1 tags 0 (never matches
// the odd step tags it must later carry, so stale reads spin correctly).
// ---------------------------------------------------------------------------
__global__ void k_init() {
    int i = blockIdx.x * blockDim.x + threadIdx.x;
    if (i < 2 * RDIM) ((unsigned long long*)g_hb)[i] = 0ull;
}

// ---------------------------------------------------------------------------
// K4 (launch #4 -> ncu target): persistent recurrence, tagged direct-load h.
//   - W entries REGISTER-resident (36 vals + 18 packed byte-offset regs/lane).
//   - NO flags, NO TMA, NO mbarriers, NO fences: h is published as
//     (tag<<32|bits) u64 via st.relaxed; consumers stage it with coalesced
//     ld.relaxed.u64 and spin per-element until tag == t. Detection IS the
//     data fetch: one L2 round trip replaces release+poll+TMA+wake.
//   - Global AND smem h are ping-pong buffered; a completed stage of h_t
//     proves all CTAs finished reading h_{t-1} -> overwrite is race-free.
//   - One __syncthreads per step (stage -> gather), nothing else.
// ---------------------------------------------------------------------------
__global__ void __launch_bounds__(NTHR, 1)
k_main() {
    __shared__ __align__(16) float sh[2][RDIM];       // 2 x 16 KB staged h

    const int tid  = threadIdx.x;
    const int lane = tid & 31;
    const int wid  = tid >> 5;
    const int slot = blockIdx.x * SLOTS_PER_CTA + wid;
    const int half = lane >> 4;
    const int row  = 2 * slot + half;
    const bool head = (lane == 0) | (lane == 16);

    // one-time: load this lane's 36 entries into registers
    float    vv[NE];
    unsigned cp[NE / 2];   // two pre-scaled byte offsets per reg
    {
        const Ent* src = g_ellp + (size_t)slot * (NSUB_MAX * 32) + lane;
#pragma unroll
        for (int i = 0; i < NE; i += 2) {
            Ent e0 = src[i * 32];
            Ent e1 = src[(i + 1) * 32];
            vv[i]     = e0.v;
            vv[i + 1] = e1.v;
            cp[i >> 1] = ((unsigned)e0.c << 2) | ((unsigned)e1.c << 18);
        }
    }

    float u_next = head ? __ldg(&g_u[row]) : 0.0f;     // u for t=0

    for (int t = 0; t < TLEN; ++t) {
        const unsigned long long* src = g_hb[t & 1];
        float* dst = sh[t & 1];

        // ---- stage h_t: 8 coalesced tagged loads per thread, spin on stale ----
        unsigned long long pv[8];
#pragma unroll
        for (int k = 0; k < 8; k++)
            pv[k] = ld_rlx64(src + tid + k * NTHR);
        const unsigned want = (unsigned)t;
#pragma unroll
        for (int k = 0; k < 8; k++) {
            while ((unsigned)(pv[k] >> 32) != want)
                pv[k] = ld_rlx64(src + tid + k * NTHR);
            dst[tid + k * NTHR] = __uint_as_float((unsigned)pv[k]);
        }
        __syncthreads();   // stage complete CTA-wide before gather

        // ---- sparse dot: values/offsets from registers, gathers from smem ----
        const char* hb = (const char*)dst;
        float a0 = 0.0f, a1 = 0.0f;
#pragma unroll
        for (int i = 0; i < NE; i += 2) {
            unsigned p = cp[i >> 1];
            a0 += vv[i]     * *(const float*)(hb + (p & 0xFFFFu));
            a1 += vv[i + 1] * *(const float*)(hb + (p >> 16));
        }
        float acc = a0 + a1;
#pragma unroll
        for (int off = 8; off; off >>= 1)
            acc += __shfl_xor_sync(0xffffffffu, acc, off);

        if (head) {
            float hv = tanh_hw(acc + u_next);          // HW MUFU.TANH
            // publish IMMEDIATELY: tagged single-word store (atomic, coherent)
            unsigned long long pub =
                ((unsigned long long)(unsigned)(t + 1) << 32)
                | (unsigned long long)__float_as_uint(hv);
            st_rlx64(&g_hb[(t + 1) & 1][row], pub);
            __stcg(g_hall + (size_t)(t + 1) * RDIM + row, hv);   // for k_out
            if (t + 1 < TLEN) u_next = __ldcg(&g_u[(size_t)(t + 1) * RDIM + row]);
        }
        // no tail sync: smem ping-pong + tag-validated staging make reuse safe
    }
}

// ---------------------------------------------------------------------------
// K5: out[t][o] = bias[o] + sum_r h_{t+1}[r] * Wout[o][r]
// ---------------------------------------------------------------------------
__global__ void k_out(const float* __restrict__ Wout, const float* __restrict__ bias,
                      float* __restrict__ out) {
    int t = blockIdx.x;
    const float4* h4 = (const float4*)(g_hall + (size_t)(t + 1) * RDIM);
    float acc[ODIM];
#pragma unroll
    for (int o = 0; o < ODIM; o++) acc[o] = 0.0f;

    for (int r4 = threadIdx.x; r4 < RDIM / 4; r4 += blockDim.x) {
        float4 h = h4[r4];
#pragma unroll
        for (int o = 0; o < ODIM; o++) {
            float4 w = __ldg((const float4*)(Wout + o * RDIM) + r4);
            acc[o] += h.x * w.x + h.y * w.y + h.z * w.z + h.w * w.w;
        }
    }
    __shared__ float red[8][ODIM];
    int wid = threadIdx.x >> 5, lane = threadIdx.x & 31;
#pragma unroll
    for (int o = 0; o < ODIM; o++) {
        float v = acc[o];
#pragma unroll
        for (int off = 16; off; off >>= 1)
            v += __shfl_xor_sync(0xffffffffu, v, off);
        if (lane == 0) red[wid][o] = v;
    }
    __syncthreads();
    if (threadIdx.x < ODIM) {
        float s = bias[threadIdx.x];
#pragma unroll
        for (int w = 0; w < 8; w++) s += red[w][threadIdx.x];
        out[t * ODIM + threadIdx.x] = s;
    }
}

// ---------------------------------------------------------------------------
extern "C" void kernel_launch(void* const* d_in, const int* in_sizes, int n_in,
                              void* d_out, int out_size) {
    (void)in_sizes; (void)n_in; (void)out_size;
    const float* x      = (const float*)d_in[0];  // [1, 2048, 8]
    const float* Win    = (const float*)d_in[1];  // [4096, 8]
    const float* W      = (const float*)d_in[2];  // [4096, 4096]
    const float* Wout_w = (const float*)d_in[3];  // [8, 4096]
    const float* Wout_b = (const float*)d_in[4];  // [8]
    float* out = (float*)d_out;                   // [1, 2048, 8]

    k_u<<<TLEN, 256>>>(x, Win);                   // launch 1
    k_prep<<<NSLOT / 8, 256>>>(W);                // launch 2
    k_init<<<(2 * RDIM + 255) / 256, 256>>>();    // launch 3
    k_main<<<NBLK, NTHR>>>();                     // launch 4 <- ncu target
    k_out<<<TLEN, 256>>>(Wout_w, Wout_b, out);    // launch 5
}